// round 1
// baseline (speedup 1.0000x reference)
#include <cuda_runtime.h>
#include <mma.h>
#include <cstdint>

using namespace nvcuda;

#define BATCH 64
#define SEQT  1024
#define IDIM  256
#define HDIM  512
#define G4    2048   // 4*H

// ---------------- scratch (device globals; no allocation allowed) ----------------
__device__ float g_xt [(size_t)BATCH * SEQT * IDIM]; // transposed input (B,T,I)
__device__ float g_xp [(size_t)BATCH * SEQT * G4];   // precomputed input gates (B*T, 4H)
__device__ float g_ys0[(size_t)BATCH * SEQT * HDIM]; // layer-0 outputs
__device__ float g_h  [2][BATCH * HDIM];             // h double buffer
__device__ unsigned g_bar_cnt;
__device__ unsigned g_bar_phase;

// ---------------- transpose: x (B,I,T) -> xt (B,T,I) ----------------
__global__ void transpose_kernel(const float* __restrict__ x) {
    __shared__ float tile[32][33];
    int b  = blockIdx.z;
    int t0 = blockIdx.x * 32;
    int i0 = blockIdx.y * 32;
    const float* xb = x + (size_t)b * IDIM * SEQT;
    #pragma unroll
    for (int k = 0; k < 32; k += 8) {
        int i = i0 + threadIdx.y + k;
        tile[threadIdx.y + k][threadIdx.x] = xb[(size_t)i * SEQT + t0 + threadIdx.x];
    }
    __syncthreads();
    float* xtb = g_xt + (size_t)b * SEQT * IDIM;
    #pragma unroll
    for (int k = 0; k < 32; k += 8) {
        int t = t0 + threadIdx.y + k;
        xtb[(size_t)t * IDIM + i0 + threadIdx.x] = tile[threadIdx.x][threadIdx.y + k];
    }
}

// ---------------- zero h buffers + barrier state ----------------
__global__ void zero_kernel() {
    int i = blockIdx.x * blockDim.x + threadIdx.x;
    float* h = &g_h[0][0];
    if (i < 2 * BATCH * HDIM) h[i] = 0.0f;
    if (i == 0) { g_bar_cnt = 0; g_bar_phase = 0; }
}

// ---------------- TF32 GEMM:  C[m,n] = sum_k A[m,k] * W[n,k] ----------------
// A: (65536, K) row-major.  W: (2048, K) row-major.  C = g_xp (65536, 2048).
#define GBM 128
#define GBN 128
#define GBK 16
#define GLDA 20   // smem leading dim (pad)

__global__ void __launch_bounds__(256) gemm_tf32_kernel(
    const float* __restrict__ A, const float* __restrict__ W, int K)
{
    __shared__ float sA[GBM][GLDA];
    __shared__ float sB[GBN][GLDA];
    int tid = threadIdx.x;
    int m0  = blockIdx.y * GBM;
    int n0  = blockIdx.x * GBN;
    int warp = tid >> 5;
    int wm = warp >> 2;   // 0..1 : 64 rows each
    int wn = warp & 3;    // 0..3 : 32 cols each

    wmma::fragment<wmma::accumulator, 16, 16, 8, float> cf[4][2];
    #pragma unroll
    for (int i = 0; i < 4; ++i)
        #pragma unroll
        for (int j = 0; j < 2; ++j)
            wmma::fill_fragment(cf[i][j], 0.0f);

    for (int k0 = 0; k0 < K; k0 += GBK) {
        #pragma unroll
        for (int i = 0; i < 2; ++i) {
            int fid = tid + i * 256;
            int r = fid >> 2, q = (fid & 3) << 2;
            float4 v = *(const float4*)&A[(size_t)(m0 + r) * K + k0 + q];
            float* d = &sA[r][q];
            d[0] = wmma::__float_to_tf32(v.x);
            d[1] = wmma::__float_to_tf32(v.y);
            d[2] = wmma::__float_to_tf32(v.z);
            d[3] = wmma::__float_to_tf32(v.w);
        }
        #pragma unroll
        for (int i = 0; i < 2; ++i) {
            int fid = tid + i * 256;
            int r = fid >> 2, q = (fid & 3) << 2;
            float4 v = *(const float4*)&W[(size_t)(n0 + r) * K + k0 + q];
            float* d = &sB[r][q];
            d[0] = wmma::__float_to_tf32(v.x);
            d[1] = wmma::__float_to_tf32(v.y);
            d[2] = wmma::__float_to_tf32(v.z);
            d[3] = wmma::__float_to_tf32(v.w);
        }
        __syncthreads();
        #pragma unroll
        for (int ks = 0; ks < GBK; ks += 8) {
            wmma::fragment<wmma::matrix_a, 16, 16, 8, wmma::precision::tf32, wmma::row_major> af[4];
            wmma::fragment<wmma::matrix_b, 16, 16, 8, wmma::precision::tf32, wmma::col_major> bf[2];
            #pragma unroll
            for (int i = 0; i < 4; ++i)
                wmma::load_matrix_sync(af[i], &sA[wm * 64 + i * 16][ks], GLDA);
            #pragma unroll
            for (int j = 0; j < 2; ++j)
                wmma::load_matrix_sync(bf[j], &sB[wn * 32 + j * 16][ks], GLDA);
            #pragma unroll
            for (int i = 0; i < 4; ++i)
                #pragma unroll
                for (int j = 0; j < 2; ++j)
                    wmma::mma_sync(cf[i][j], af[i], bf[j], cf[i][j]);
        }
        __syncthreads();
    }
    #pragma unroll
    for (int i = 0; i < 4; ++i)
        #pragma unroll
        for (int j = 0; j < 2; ++j)
            wmma::store_matrix_sync(
                &g_xp[(size_t)(m0 + wm * 64 + i * 16) * G4 + n0 + wn * 32 + j * 16],
                cf[i][j], G4, wmma::mem_row_major);
}

// ---------------- persistent LSTM scan (one layer) ----------------
// 128 CTAs x 128 threads. CTA (rt, ct): batch rows rt*16..+15, hidden cols ct*16..+15.
// Gate tile: 16 (batch) x 64 (4 gates x 16 hidden), K = 512 over h.
#define SCAN_NB      128
#define SCAN_THREADS 128
#define WLD 520   // W/H smem leading dims
#define GLD 72    // gate tile leading dim

__global__ void __launch_bounds__(SCAN_THREADS, 1) scan_kernel(
    const float* __restrict__ W_hh, const float* __restrict__ b_ih,
    const float* __restrict__ b_hh, float* __restrict__ ys,
    float* __restrict__ hid_out, float* __restrict__ cell_out)
{
    extern __shared__ float sm[];
    float* sW    = sm;                    // 64 x 520
    float* sH    = sW + 64 * WLD;         // 16 x 520
    float* sG    = sH + 16 * WLD;         // 16 x 72
    float* sBias = sG + 16 * GLD;         // 64

    int tid  = threadIdx.x;
    int cta  = blockIdx.x;
    int rb0  = (cta >> 5) * 16;   // batch-tile origin (4 tiles)
    int j0   = (cta & 31) * 16;   // hidden-tile origin (32 tiles)
    int warp = tid >> 5;          // 4 warps: each owns one 16-col gate n-frag

    // cache W_hh slice (TF32) in smem for the entire scan
    for (int idx = tid; idx < 64 * 512; idx += SCAN_THREADS) {
        int n = idx >> 9, k = idx & 511;
        int g = (n >> 4) * HDIM + j0 + (n & 15);
        sW[n * WLD + k] = wmma::__float_to_tf32(W_hh[(size_t)g * HDIM + k]);
    }
    if (tid < 64) {
        int n = tid;
        int g = (n >> 4) * HDIM + j0 + (n & 15);
        sBias[n] = b_ih[g] + b_hh[g];
    }
    __syncthreads();

    float creg[2] = {0.0f, 0.0f};   // this thread's cell state: entries tid and tid+128

    for (int t = 0; t < SEQT; ++t) {
        const float* hsrc = g_h[t & 1];
        float*       hdst = g_h[(t + 1) & 1];

        // stage h tile (16 x 512) -> TF32 smem
        for (int q = tid; q < 16 * 128; q += SCAN_THREADS) {
            int b = q >> 7; int c4 = (q & 127) << 2;
            float4 v = *(const float4*)&hsrc[(rb0 + b) * HDIM + c4];
            float* d = &sH[b * WLD + c4];
            d[0] = wmma::__float_to_tf32(v.x);
            d[1] = wmma::__float_to_tf32(v.y);
            d[2] = wmma::__float_to_tf32(v.z);
            d[3] = wmma::__float_to_tf32(v.w);
        }
        // stage gate init: xp + (b_ih + b_hh)
        for (int q = tid; q < 16 * 64; q += SCAN_THREADS) {
            int b = q >> 6, n = q & 63;
            int g = (n >> 4) * HDIM + j0 + (n & 15);
            sG[b * GLD + n] =
                g_xp[((size_t)(rb0 + b) * SEQT + t) * G4 + g] + sBias[n];
        }
        __syncthreads();

        // gates += h @ W^T (warp = one 16-wide n-frag, full K=512)
        wmma::fragment<wmma::accumulator, 16, 16, 8, float> cf;
        wmma::load_matrix_sync(cf, &sG[warp * 16], GLD, wmma::mem_row_major);
        #pragma unroll 8
        for (int kt = 0; kt < 64; ++kt) {
            wmma::fragment<wmma::matrix_a, 16, 16, 8, wmma::precision::tf32, wmma::row_major> af;
            wmma::fragment<wmma::matrix_b, 16, 16, 8, wmma::precision::tf32, wmma::col_major> bf;
            wmma::load_matrix_sync(af, &sH[kt * 8], WLD);
            wmma::load_matrix_sync(bf, &sW[warp * 16 * WLD + kt * 8], WLD);
            wmma::mma_sync(cf, af, bf, cf);
        }
        wmma::store_matrix_sync(&sG[warp * 16], cf, GLD, wmma::mem_row_major);
        __syncthreads();

        // elementwise gates -> c, h  (each thread owns 2 (b,j) cells)
        #pragma unroll
        for (int e = 0; e < 2; ++e) {
            int idx = tid + e * 128;
            int b = idx >> 4, jj = idx & 15;
            float gi = sG[b * GLD + jj];
            float gf = sG[b * GLD + 16 + jj];
            float gg = sG[b * GLD + 32 + jj];
            float go = sG[b * GLD + 48 + jj];
            float si = 1.0f / (1.0f + __expf(-gi));
            float sf = 1.0f / (1.0f + __expf(-gf));
            float tg = tanhf(gg);
            float so = 1.0f / (1.0f + __expf(-go));
            float c  = sf * creg[e] + si * tg;
            creg[e]  = c;
            float h  = so * tanhf(c);
            int bg = rb0 + b, jg = j0 + jj;
            hdst[bg * HDIM + jg] = h;
            ys[((size_t)bg * SEQT + t) * HDIM + jg] = h;
            if (t == SEQT - 1) {
                hid_out [bg * HDIM + jg] = h;
                cell_out[bg * HDIM + jg] = c;
            }
        }

        // grid-wide barrier (skip after last step)
        if (t != SEQT - 1) {
            __syncthreads();
            if (tid == 0) {
                __threadfence();
                unsigned old = atomicAdd(&g_bar_cnt, 1);
                if (old == SCAN_NB - 1) {
                    atomicExch(&g_bar_cnt, 0);
                    __threadfence();
                    atomicAdd(&g_bar_phase, 1);
                } else {
                    while (*(volatile unsigned*)&g_bar_phase < (unsigned)(t + 1))
                        __nanosleep(32);
                    __threadfence();
                }
            }
            __syncthreads();
        }
    }
}

// ---------------- launch ----------------
extern "C" void kernel_launch(void* const* d_in, const int* in_sizes, int n_in,
                              void* d_out, int out_size)
{
    const float* x     = (const float*)d_in[0];
    const float* W_ih0 = (const float*)d_in[1];
    const float* W_hh0 = (const float*)d_in[2];
    const float* b_ih0 = (const float*)d_in[3];
    const float* b_hh0 = (const float*)d_in[4];
    const float* W_ih1 = (const float*)d_in[5];
    const float* W_hh1 = (const float*)d_in[6];
    const float* b_ih1 = (const float*)d_in[7];
    const float* b_hh1 = (const float*)d_in[8];
    float* out = (float*)d_out;

    float *p_xt = nullptr, *p_ys0 = nullptr;
    cudaGetSymbolAddress((void**)&p_xt,  g_xt);
    cudaGetSymbolAddress((void**)&p_ys0, g_ys0);

    const size_t OUT_BTH = (size_t)BATCH * SEQT * HDIM;   // 33,554,432
    float* hid0  = out + OUT_BTH;
    float* hid1  = hid0 + BATCH * HDIM;
    float* cell0 = out + OUT_BTH + 2 * BATCH * HDIM;
    float* cell1 = cell0 + BATCH * HDIM;

    const int scan_smem = (64 * WLD + 16 * WLD + 16 * GLD + 64) * sizeof(float);
    cudaFuncSetAttribute(scan_kernel, cudaFuncAttributeMaxDynamicSharedMemorySize, scan_smem);

    // 1) transpose x -> (B,T,I)
    transpose_kernel<<<dim3(SEQT / 32, IDIM / 32, BATCH), dim3(32, 8)>>>(x);

    // 2) xp0 = xt @ W_ih0^T
    gemm_tf32_kernel<<<dim3(G4 / GBN, (BATCH * SEQT) / GBM), 256>>>(p_xt, W_ih0, IDIM);

    // 3) layer-0 scan
    zero_kernel<<<256, 256>>>();
    scan_kernel<<<SCAN_NB, SCAN_THREADS, scan_smem>>>(W_hh0, b_ih0, b_hh0, p_ys0, hid0, cell0);

    // 4) xp1 = ys0 @ W_ih1^T
    gemm_tf32_kernel<<<dim3(G4 / GBN, (BATCH * SEQT) / GBM), 256>>>(p_ys0, W_ih1, HDIM);

    // 5) layer-1 scan (writes directly into d_out)
    zero_kernel<<<256, 256>>>();
    scan_kernel<<<SCAN_NB, SCAN_THREADS, scan_smem>>>(W_hh1, b_ih1, b_hh1, out, hid1, cell1);
}

// round 2
// speedup vs baseline: 1.1812x; 1.1812x over previous
#include <cuda_runtime.h>
#include <mma.h>
#include <cstdint>

using namespace nvcuda;

#define BATCH 64
#define SEQT  1024
#define IDIM  256
#define HDIM  512
#define G4    2048   // 4*H

// ---------------- scratch (device globals; no allocation allowed) ----------------
__device__ float g_xt [(size_t)BATCH * SEQT * IDIM]; // transposed input (B,T,I)
__device__ float g_xp [(size_t)BATCH * SEQT * G4];   // precomputed input gates (B*T, 4H)
__device__ float g_ys0[(size_t)BATCH * SEQT * HDIM]; // layer-0 outputs
__device__ float g_h  [2][BATCH * HDIM];             // h double buffer
__device__ unsigned g_cnt[SEQT];                     // per-step barrier counters

// ---------------- transpose: x (B,I,T) -> xt (B,T,I) ----------------
__global__ void transpose_kernel(const float* __restrict__ x) {
    __shared__ float tile[32][33];
    int b  = blockIdx.z;
    int t0 = blockIdx.x * 32;
    int i0 = blockIdx.y * 32;
    const float* xb = x + (size_t)b * IDIM * SEQT;
    #pragma unroll
    for (int k = 0; k < 32; k += 8) {
        int i = i0 + threadIdx.y + k;
        tile[threadIdx.y + k][threadIdx.x] = xb[(size_t)i * SEQT + t0 + threadIdx.x];
    }
    __syncthreads();
    float* xtb = g_xt + (size_t)b * SEQT * IDIM;
    #pragma unroll
    for (int k = 0; k < 32; k += 8) {
        int t = t0 + threadIdx.y + k;
        xtb[(size_t)t * IDIM + i0 + threadIdx.x] = tile[threadIdx.x][threadIdx.y + k];
    }
}

// ---------------- zero h buffers + barrier counters ----------------
__global__ void zero_kernel() {
    int i = blockIdx.x * blockDim.x + threadIdx.x;
    int n = 2 * BATCH * HDIM;
    float* h = &g_h[0][0];
    for (int k = i; k < n; k += gridDim.x * blockDim.x) h[k] = 0.0f;
    for (int k = i; k < SEQT; k += gridDim.x * blockDim.x) g_cnt[k] = 0u;
}

// ---------------- TF32 GEMM:  C[m,n] = sum_k A[m,k] * W[n,k] ----------------
// A: (65536, K) row-major.  W: (2048, K) row-major.  C: (65536, 2048).
#define GBM 128
#define GBN 128
#define GBK 32
#define SLD 40   // smem leading dim (32 + 8 pad)

__global__ void __launch_bounds__(256) gemm_tf32_kernel(
    const float* __restrict__ A, const float* __restrict__ W,
    float* __restrict__ C, int K)
{
    extern __shared__ float gs[];   // 2 stages x (sA 128xSLD + sB 128xSLD)
    int tid = threadIdx.x;
    int m0  = blockIdx.y * GBM;
    int n0  = blockIdx.x * GBN;
    int warp = tid >> 5;
    int wm = warp >> 2;   // 0..1 : 64 rows each
    int wn = warp & 3;    // 0..3 : 32 cols each

    wmma::fragment<wmma::accumulator, 16, 16, 8, float> cf[4][2];
    #pragma unroll
    for (int i = 0; i < 4; ++i)
        #pragma unroll
        for (int j = 0; j < 2; ++j)
            wmma::fill_fragment(cf[i][j], 0.0f);

    float4 ra[4], rb[4];

    auto ldg_tile = [&](int k0) {
        #pragma unroll
        for (int i = 0; i < 4; ++i) {
            int fid = tid + i * 256;
            int r = fid >> 3, cq = (fid & 7) << 2;
            ra[i] = *(const float4*)&A[(size_t)(m0 + r) * K + k0 + cq];
            rb[i] = *(const float4*)&W[(size_t)(n0 + r) * K + k0 + cq];
        }
    };
    auto sts_tile = [&](int buf) {
        float* sA = gs + buf * 2 * GBM * SLD;
        float* sB = sA + GBM * SLD;
        #pragma unroll
        for (int i = 0; i < 4; ++i) {
            int fid = tid + i * 256;
            int r = fid >> 3, cq = (fid & 7) << 2;
            float* d = &sA[r * SLD + cq];
            d[0] = wmma::__float_to_tf32(ra[i].x);
            d[1] = wmma::__float_to_tf32(ra[i].y);
            d[2] = wmma::__float_to_tf32(ra[i].z);
            d[3] = wmma::__float_to_tf32(ra[i].w);
            float* e = &sB[r * SLD + cq];
            e[0] = wmma::__float_to_tf32(rb[i].x);
            e[1] = wmma::__float_to_tf32(rb[i].y);
            e[2] = wmma::__float_to_tf32(rb[i].z);
            e[3] = wmma::__float_to_tf32(rb[i].w);
        }
    };

    ldg_tile(0);
    sts_tile(0);
    __syncthreads();

    int nk = K / GBK;
    int buf = 0;
    for (int kt = 0; kt < nk; ++kt) {
        bool has_next = (kt + 1) < nk;
        if (has_next) ldg_tile((kt + 1) * GBK);

        float* sA = gs + buf * 2 * GBM * SLD;
        float* sB = sA + GBM * SLD;
        #pragma unroll
        for (int ks = 0; ks < GBK; ks += 8) {
            wmma::fragment<wmma::matrix_a, 16, 16, 8, wmma::precision::tf32, wmma::row_major> af[4];
            wmma::fragment<wmma::matrix_b, 16, 16, 8, wmma::precision::tf32, wmma::col_major> bf[2];
            #pragma unroll
            for (int i = 0; i < 4; ++i)
                wmma::load_matrix_sync(af[i], &sA[(wm * 64 + i * 16) * SLD + ks], SLD);
            #pragma unroll
            for (int j = 0; j < 2; ++j)
                wmma::load_matrix_sync(bf[j], &sB[(wn * 32 + j * 16) * SLD + ks], SLD);
            #pragma unroll
            for (int i = 0; i < 4; ++i)
                #pragma unroll
                for (int j = 0; j < 2; ++j)
                    wmma::mma_sync(cf[i][j], af[i], bf[j], cf[i][j]);
        }
        if (has_next) sts_tile(buf ^ 1);
        __syncthreads();
        buf ^= 1;
    }
    #pragma unroll
    for (int i = 0; i < 4; ++i)
        #pragma unroll
        for (int j = 0; j < 2; ++j)
            wmma::store_matrix_sync(
                &C[(size_t)(m0 + wm * 64 + i * 16) * G4 + n0 + wn * 32 + j * 16],
                cf[i][j], G4, wmma::mem_row_major);
}

// ---------------- persistent LSTM scan (one layer) ----------------
// 128 CTAs x 128 threads. CTA: batch rows rb0..+15, hidden cols j0..+15.
// Gate tile: 16 (batch) x 64 (4 gates x 16 hidden), K = 512 over h.
#define SCAN_NB      128
#define SCAN_THREADS 128
#define WLD 520   // W/H smem leading dims
#define GLD 72    // gate tile leading dim

__global__ void __launch_bounds__(SCAN_THREADS, 1) scan_kernel(
    const float* __restrict__ W_hh, const float* __restrict__ b_ih,
    const float* __restrict__ b_hh, float* __restrict__ ys,
    float* __restrict__ hid_out, float* __restrict__ cell_out)
{
    extern __shared__ float sm[];
    float* sW    = sm;                    // 64 x 520
    float* sH    = sW + 64 * WLD;         // 16 x 520
    float* sG    = sH + 16 * WLD;         // 16 x 72
    float* sBias = sG + 16 * GLD;         // 64

    int tid  = threadIdx.x;
    int cta  = blockIdx.x;
    int rb0  = (cta >> 5) * 16;   // batch-tile origin (4 tiles)
    int j0   = (cta & 31) * 16;   // hidden-tile origin (32 tiles)
    int warp = tid >> 5;          // 4 warps: each owns one 16-col gate n-frag

    // cache W_hh slice (TF32) in smem for the entire scan
    for (int idx = tid; idx < 64 * 512; idx += SCAN_THREADS) {
        int n = idx >> 9, k = idx & 511;
        int g = (n >> 4) * HDIM + j0 + (n & 15);
        sW[n * WLD + k] = wmma::__float_to_tf32(W_hh[(size_t)g * HDIM + k]);
    }
    if (tid < 64) {
        int n = tid;
        int g = (n >> 4) * HDIM + j0 + (n & 15);
        sBias[n] = b_ih[g] + b_hh[g];
    }
    __syncthreads();

    float creg[2] = {0.0f, 0.0f};   // this thread's cell state

    // prefetch xp for t = 0
    float rxp[8];
    #pragma unroll
    for (int e = 0; e < 8; ++e) {
        int idx = tid + e * 128;
        int b = idx >> 6, n = idx & 63;
        int g = (n >> 4) * HDIM + j0 + (n & 15);
        rxp[e] = g_xp[((size_t)(rb0 + b) * SEQT + 0) * G4 + g];
    }

    for (int t = 0; t < SEQT; ++t) {
        const float* hsrc = g_h[t & 1];
        float*       hdst = g_h[(t + 1) & 1];

        // stage h tile (16 x 512) -> TF32 smem
        #pragma unroll 4
        for (int q = tid; q < 16 * 128; q += SCAN_THREADS) {
            int b = q >> 7; int c4 = (q & 127) << 2;
            float4 v = *(const float4*)&hsrc[(rb0 + b) * HDIM + c4];
            float* d = &sH[b * WLD + c4];
            d[0] = wmma::__float_to_tf32(v.x);
            d[1] = wmma::__float_to_tf32(v.y);
            d[2] = wmma::__float_to_tf32(v.z);
            d[3] = wmma::__float_to_tf32(v.w);
        }
        // stage gate init from prefetched xp + bias
        #pragma unroll
        for (int e = 0; e < 8; ++e) {
            int idx = tid + e * 128;
            int b = idx >> 6, n = idx & 63;
            sG[b * GLD + n] = rxp[e] + sBias[n];
        }
        __syncthreads();

        // gates += h @ W^T : 4 interleaved accumulators break the dep chain
        wmma::fragment<wmma::accumulator, 16, 16, 8, float> acc[4];
        wmma::load_matrix_sync(acc[0], &sG[warp * 16], GLD, wmma::mem_row_major);
        wmma::fill_fragment(acc[1], 0.0f);
        wmma::fill_fragment(acc[2], 0.0f);
        wmma::fill_fragment(acc[3], 0.0f);
        #pragma unroll 8
        for (int kt = 0; kt < 64; ++kt) {
            wmma::fragment<wmma::matrix_a, 16, 16, 8, wmma::precision::tf32, wmma::row_major> af;
            wmma::fragment<wmma::matrix_b, 16, 16, 8, wmma::precision::tf32, wmma::col_major> bf;
            wmma::load_matrix_sync(af, &sH[kt * 8], WLD);
            wmma::load_matrix_sync(bf, &sW[warp * 16 * WLD + kt * 8], WLD);
            wmma::mma_sync(acc[kt & 3], af, bf, acc[kt & 3]);
        }
        #pragma unroll
        for (int i = 0; i < acc[0].num_elements; ++i)
            acc[0].x[i] += acc[1].x[i] + acc[2].x[i] + acc[3].x[i];
        wmma::store_matrix_sync(&sG[warp * 16], acc[0], GLD, wmma::mem_row_major);
        __syncthreads();

        // elementwise gates -> c, h  (each thread owns 2 (b,j) cells)
        #pragma unroll
        for (int e = 0; e < 2; ++e) {
            int idx = tid + e * 128;
            int b = idx >> 4, jj = idx & 15;
            float gi = sG[b * GLD + jj];
            float gf = sG[b * GLD + 16 + jj];
            float gg = sG[b * GLD + 32 + jj];
            float go = sG[b * GLD + 48 + jj];
            float si = 1.0f / (1.0f + __expf(-gi));
            float sf = 1.0f / (1.0f + __expf(-gf));
            float tg = tanhf(gg);
            float so = 1.0f / (1.0f + __expf(-go));
            float c  = sf * creg[e] + si * tg;
            creg[e]  = c;
            float h  = so * tanhf(c);
            int bg = rb0 + b, jg = j0 + jj;
            hdst[bg * HDIM + jg] = h;
            ys[((size_t)bg * SEQT + t) * HDIM + jg] = h;
            if (t == SEQT - 1) {
                hid_out [bg * HDIM + jg] = h;
                cell_out[bg * HDIM + jg] = c;
            }
        }

        // grid-wide barrier with xp prefetch overlapped inside arrive->wait window
        if (t != SEQT - 1) {
            __syncthreads();                 // all h stores of this CTA issued
            bool last = false;
            if (tid == 0) {
                __threadfence();             // release (cumulative over block)
                unsigned old = atomicAdd(&g_cnt[t], 1u);
                last = (old == SCAN_NB - 1);
            }
            // prefetch next step's xp while other CTAs arrive
            #pragma unroll
            for (int e = 0; e < 8; ++e) {
                int idx = tid + e * 128;
                int b = idx >> 6, n = idx & 63;
                int g = (n >> 4) * HDIM + j0 + (n & 15);
                rxp[e] = g_xp[((size_t)(rb0 + b) * SEQT + (t + 1)) * G4 + g];
            }
            if (tid == 0) {
                if (!last) {
                    while (*(volatile unsigned*)&g_cnt[t] < (unsigned)SCAN_NB)
                        __nanosleep(20);
                }
                __threadfence();             // acquire
            }
            __syncthreads();
        }
    }
}

// ---------------- launch ----------------
extern "C" void kernel_launch(void* const* d_in, const int* in_sizes, int n_in,
                              void* d_out, int out_size)
{
    const float* x     = (const float*)d_in[0];
    const float* W_ih0 = (const float*)d_in[1];
    const float* W_hh0 = (const float*)d_in[2];
    const float* b_ih0 = (const float*)d_in[3];
    const float* b_hh0 = (const float*)d_in[4];
    const float* W_ih1 = (const float*)d_in[5];
    const float* W_hh1 = (const float*)d_in[6];
    const float* b_ih1 = (const float*)d_in[7];
    const float* b_hh1 = (const float*)d_in[8];
    float* out = (float*)d_out;

    float *p_xt = nullptr, *p_ys0 = nullptr, *p_xp = nullptr;
    cudaGetSymbolAddress((void**)&p_xt,  g_xt);
    cudaGetSymbolAddress((void**)&p_ys0, g_ys0);
    cudaGetSymbolAddress((void**)&p_xp,  g_xp);

    const size_t OUT_BTH = (size_t)BATCH * SEQT * HDIM;   // 33,554,432
    float* hid0  = out + OUT_BTH;
    float* hid1  = hid0 + BATCH * HDIM;
    float* cell0 = out + OUT_BTH + 2 * BATCH * HDIM;
    float* cell1 = cell0 + BATCH * HDIM;

    const int scan_smem = (64 * WLD + 16 * WLD + 16 * GLD + 64) * sizeof(float);
    cudaFuncSetAttribute(scan_kernel, cudaFuncAttributeMaxDynamicSharedMemorySize, scan_smem);
    const int gemm_smem = 2 * 2 * GBM * SLD * sizeof(float);   // 81920
    cudaFuncSetAttribute(gemm_tf32_kernel, cudaFuncAttributeMaxDynamicSharedMemorySize, gemm_smem);

    // 1) transpose x -> (B,T,I)
    transpose_kernel<<<dim3(SEQT / 32, IDIM / 32, BATCH), dim3(32, 8)>>>(x);

    // 2) xp0 = xt @ W_ih0^T
    gemm_tf32_kernel<<<dim3(G4 / GBN, (BATCH * SEQT) / GBM), 256, gemm_smem>>>(p_xt, W_ih0, p_xp, IDIM);

    // 3) layer-0 scan
    zero_kernel<<<256, 256>>>();
    scan_kernel<<<SCAN_NB, SCAN_THREADS, scan_smem>>>(W_hh0, b_ih0, b_hh0, p_ys0, hid0, cell0);

    // 4) xp1 = ys0 @ W_ih1^T
    gemm_tf32_kernel<<<dim3(G4 / GBN, (BATCH * SEQT) / GBM), 256, gemm_smem>>>(p_ys0, W_ih1, p_xp, HDIM);

    // 5) layer-1 scan (writes directly into d_out)
    zero_kernel<<<256, 256>>>();
    scan_kernel<<<SCAN_NB, SCAN_THREADS, scan_smem>>>(W_hh1, b_ih1, b_hh1, out, hid1, cell1);
}

// round 3
// speedup vs baseline: 1.4755x; 1.2492x over previous
#include <cuda_runtime.h>
#include <mma.h>
#include <cstdint>

using namespace nvcuda;

#define BATCH 64
#define SEQT  1024
#define IDIM  256
#define HDIM  512
#define G4    2048   // 4*H

// ---------------- scratch (device globals; no allocation allowed) ----------------
__device__ float g_xt [(size_t)BATCH * SEQT * IDIM]; // transposed input (B,T,I)
__device__ float g_xp [(size_t)BATCH * SEQT * G4];   // precomputed input gates (B*T, 4H)
__device__ float g_ys0[(size_t)BATCH * SEQT * HDIM]; // layer-0 outputs
__device__ float g_h  [2][BATCH * HDIM];             // h double buffer
__device__ unsigned g_cnt[4][SEQT];                  // per-group per-step barrier counters

// ---------------- transpose: x (B,I,T) -> xt (B,T,I) ----------------
__global__ void transpose_kernel(const float* __restrict__ x) {
    __shared__ float tile[32][33];
    int b  = blockIdx.z;
    int t0 = blockIdx.x * 32;
    int i0 = blockIdx.y * 32;
    const float* xb = x + (size_t)b * IDIM * SEQT;
    #pragma unroll
    for (int k = 0; k < 32; k += 8) {
        int i = i0 + threadIdx.y + k;
        tile[threadIdx.y + k][threadIdx.x] = xb[(size_t)i * SEQT + t0 + threadIdx.x];
    }
    __syncthreads();
    float* xtb = g_xt + (size_t)b * SEQT * IDIM;
    #pragma unroll
    for (int k = 0; k < 32; k += 8) {
        int t = t0 + threadIdx.y + k;
        xtb[(size_t)t * IDIM + i0 + threadIdx.x] = tile[threadIdx.x][threadIdx.y + k];
    }
}

// ---------------- zero h buffers + barrier counters ----------------
__global__ void zero_kernel() {
    int i = blockIdx.x * blockDim.x + threadIdx.x;
    int n = 2 * BATCH * HDIM;
    float* h = &g_h[0][0];
    for (int k = i; k < n; k += gridDim.x * blockDim.x) h[k] = 0.0f;
    unsigned* c = &g_cnt[0][0];
    for (int k = i; k < 4 * SEQT; k += gridDim.x * blockDim.x) c[k] = 0u;
}

// ---------------- TF32 GEMM:  C[m,n] = sum_k A[m,k] * W[n,k] ----------------
#define GBM 128
#define GBN 128
#define GBK 32
#define SLD 40   // smem leading dim (32 + 8 pad)

__global__ void __launch_bounds__(256) gemm_tf32_kernel(
    const float* __restrict__ A, const float* __restrict__ W,
    float* __restrict__ C, int K)
{
    extern __shared__ float gs[];   // 2 stages x (sA 128xSLD + sB 128xSLD)
    int tid = threadIdx.x;
    int m0  = blockIdx.y * GBM;
    int n0  = blockIdx.x * GBN;
    int warp = tid >> 5;
    int wm = warp >> 2;   // 0..1 : 64 rows each
    int wn = warp & 3;    // 0..3 : 32 cols each

    wmma::fragment<wmma::accumulator, 16, 16, 8, float> cf[4][2];
    #pragma unroll
    for (int i = 0; i < 4; ++i)
        #pragma unroll
        for (int j = 0; j < 2; ++j)
            wmma::fill_fragment(cf[i][j], 0.0f);

    float4 ra[4], rb[4];

    auto ldg_tile = [&](int k0) {
        #pragma unroll
        for (int i = 0; i < 4; ++i) {
            int fid = tid + i * 256;
            int r = fid >> 3, cq = (fid & 7) << 2;
            ra[i] = *(const float4*)&A[(size_t)(m0 + r) * K + k0 + cq];
            rb[i] = *(const float4*)&W[(size_t)(n0 + r) * K + k0 + cq];
        }
    };
    auto sts_tile = [&](int buf) {
        float* sA = gs + buf * 2 * GBM * SLD;
        float* sB = sA + GBM * SLD;
        #pragma unroll
        for (int i = 0; i < 4; ++i) {
            int fid = tid + i * 256;
            int r = fid >> 3, cq = (fid & 7) << 2;
            float* d = &sA[r * SLD + cq];
            d[0] = wmma::__float_to_tf32(ra[i].x);
            d[1] = wmma::__float_to_tf32(ra[i].y);
            d[2] = wmma::__float_to_tf32(ra[i].z);
            d[3] = wmma::__float_to_tf32(ra[i].w);
            float* e = &sB[r * SLD + cq];
            e[0] = wmma::__float_to_tf32(rb[i].x);
            e[1] = wmma::__float_to_tf32(rb[i].y);
            e[2] = wmma::__float_to_tf32(rb[i].z);
            e[3] = wmma::__float_to_tf32(rb[i].w);
        }
    };

    ldg_tile(0);
    sts_tile(0);
    __syncthreads();

    int nk = K / GBK;
    int buf = 0;
    for (int kt = 0; kt < nk; ++kt) {
        bool has_next = (kt + 1) < nk;
        if (has_next) ldg_tile((kt + 1) * GBK);

        float* sA = gs + buf * 2 * GBM * SLD;
        float* sB = sA + GBM * SLD;
        #pragma unroll
        for (int ks = 0; ks < GBK; ks += 8) {
            wmma::fragment<wmma::matrix_a, 16, 16, 8, wmma::precision::tf32, wmma::row_major> af[4];
            wmma::fragment<wmma::matrix_b, 16, 16, 8, wmma::precision::tf32, wmma::col_major> bf[2];
            #pragma unroll
            for (int i = 0; i < 4; ++i)
                wmma::load_matrix_sync(af[i], &sA[(wm * 64 + i * 16) * SLD + ks], SLD);
            #pragma unroll
            for (int j = 0; j < 2; ++j)
                wmma::load_matrix_sync(bf[j], &sB[(wn * 32 + j * 16) * SLD + ks], SLD);
            #pragma unroll
            for (int i = 0; i < 4; ++i)
                #pragma unroll
                for (int j = 0; j < 2; ++j)
                    wmma::mma_sync(cf[i][j], af[i], bf[j], cf[i][j]);
        }
        if (has_next) sts_tile(buf ^ 1);
        __syncthreads();
        buf ^= 1;
    }
    #pragma unroll
    for (int i = 0; i < 4; ++i)
        #pragma unroll
        for (int j = 0; j < 2; ++j)
            wmma::store_matrix_sync(
                &C[(size_t)(m0 + wm * 64 + i * 16) * G4 + n0 + wn * 32 + j * 16],
                cf[i][j], G4, wmma::mem_row_major);
}

// ---------------- persistent LSTM scan (one layer) ----------------
// 128 CTAs x 256 threads. CTA: batch rows rb0..+15, hidden cols j0..+15.
// Gate tile: 16 (batch) x 64 (4 gates x 16 hidden), K = 512 split over 2 warp sets.
// Barrier: per batch-group (32 CTAs), release/acquire atomics, no L1 flush.
#define SCAN_NB      128
#define SCAN_THREADS 256
#define SCAN_GRP     32     // CTAs per barrier group
#define WLD 520   // W/H smem leading dims
#define GLD 72    // gate tile leading dim

__global__ void __launch_bounds__(SCAN_THREADS, 1) scan_kernel(
    const float* __restrict__ W_hh, const float* __restrict__ b_ih,
    const float* __restrict__ b_hh, float* __restrict__ ys,
    float* __restrict__ hid_out, float* __restrict__ cell_out)
{
    extern __shared__ float sm[];
    float* sW    = sm;                    // 64 x 520
    float* sH    = sW + 64 * WLD;         // 16 x 520
    float* sG0   = sH + 16 * WLD;         // 16 x 72  (K-half 0, includes xp+bias)
    float* sG1   = sG0 + 16 * GLD;        // 16 x 72  (K-half 1)
    float* sBias = sG1 + 16 * GLD;        // 64

    int tid  = threadIdx.x;
    int cta  = blockIdx.x;
    int grp  = cta >> 5;          // batch group 0..3
    int rb0  = grp * 16;          // batch-tile origin
    int j0   = (cta & 31) * 16;   // hidden-tile origin
    int warp = tid >> 5;          // 8 warps
    int wn   = warp & 3;          // gate n-frag 0..3
    int half = warp >> 2;         // K half 0/1
    int kb   = half * 256;        // K base for this warp

    // cache W_hh slice (TF32) in smem for the entire scan
    for (int idx = tid; idx < 64 * 512; idx += SCAN_THREADS) {
        int n = idx >> 9, k = idx & 511;
        int g = (n >> 4) * HDIM + j0 + (n & 15);
        sW[n * WLD + k] = wmma::__float_to_tf32(W_hh[(size_t)g * HDIM + k]);
    }
    if (tid < 64) {
        int n = tid;
        int g = (n >> 4) * HDIM + j0 + (n & 15);
        sBias[n] = b_ih[g] + b_hh[g];
    }
    __syncthreads();

    float creg = 0.0f;   // this thread's cell (b = tid>>4, jj = tid&15)

    // prefetch xp for t = 0
    float rxp[4];
    #pragma unroll
    for (int e = 0; e < 4; ++e) {
        int idx = tid + e * 256;
        int b = idx >> 6, n = idx & 63;
        int g = (n >> 4) * HDIM + j0 + (n & 15);
        rxp[e] = g_xp[((size_t)(rb0 + b) * SEQT + 0) * G4 + g];
    }

    for (int t = 0; t < SEQT; ++t) {
        const float* hsrc = g_h[t & 1];
        float*       hdst = g_h[(t + 1) & 1];

        // stage h tile (16 x 512) -> TF32 smem; __ldcv bypasses (possibly stale) L1
        #pragma unroll
        for (int e = 0; e < 8; ++e) {
            int q = tid + e * 256;
            int b = q >> 7; int c4 = (q & 127) << 2;
            float4 v = __ldcv((const float4*)&hsrc[(rb0 + b) * HDIM + c4]);
            float* d = &sH[b * WLD + c4];
            d[0] = wmma::__float_to_tf32(v.x);
            d[1] = wmma::__float_to_tf32(v.y);
            d[2] = wmma::__float_to_tf32(v.z);
            d[3] = wmma::__float_to_tf32(v.w);
        }
        // stage gate init from prefetched xp + bias
        #pragma unroll
        for (int e = 0; e < 4; ++e) {
            int idx = tid + e * 256;
            int b = idx >> 6, n = idx & 63;
            sG0[b * GLD + n] = rxp[e] + sBias[n];
        }
        __syncthreads();

        // gates += h @ W^T over this warp's K half; 4 interleaved accumulators
        wmma::fragment<wmma::accumulator, 16, 16, 8, float> acc[4];
        if (half == 0)
            wmma::load_matrix_sync(acc[0], &sG0[wn * 16], GLD, wmma::mem_row_major);
        else
            wmma::fill_fragment(acc[0], 0.0f);
        wmma::fill_fragment(acc[1], 0.0f);
        wmma::fill_fragment(acc[2], 0.0f);
        wmma::fill_fragment(acc[3], 0.0f);
        #pragma unroll 8
        for (int kt = 0; kt < 32; ++kt) {
            wmma::fragment<wmma::matrix_a, 16, 16, 8, wmma::precision::tf32, wmma::row_major> af;
            wmma::fragment<wmma::matrix_b, 16, 16, 8, wmma::precision::tf32, wmma::col_major> bf;
            wmma::load_matrix_sync(af, &sH[kb + kt * 8], WLD);
            wmma::load_matrix_sync(bf, &sW[wn * 16 * WLD + kb + kt * 8], WLD);
            wmma::mma_sync(acc[kt & 3], af, bf, acc[kt & 3]);
        }
        #pragma unroll
        for (int i = 0; i < acc[0].num_elements; ++i)
            acc[0].x[i] += acc[1].x[i] + acc[2].x[i] + acc[3].x[i];
        wmma::store_matrix_sync((half == 0 ? &sG0[wn * 16] : &sG1[wn * 16]),
                                acc[0], GLD, wmma::mem_row_major);
        __syncthreads();

        // elementwise gates -> c, h  (each thread owns 1 (b,j) cell)
        {
            int b = tid >> 4, jj = tid & 15;
            float gi = sG0[b * GLD + jj]      + sG1[b * GLD + jj];
            float gf = sG0[b * GLD + 16 + jj] + sG1[b * GLD + 16 + jj];
            float gg = sG0[b * GLD + 32 + jj] + sG1[b * GLD + 32 + jj];
            float go = sG0[b * GLD + 48 + jj] + sG1[b * GLD + 48 + jj];
            float si = 1.0f / (1.0f + __expf(-gi));
            float sf = 1.0f / (1.0f + __expf(-gf));
            float tg = tanhf(gg);
            float so = 1.0f / (1.0f + __expf(-go));
            float c  = sf * creg + si * tg;
            creg = c;
            float h  = so * tanhf(c);
            int bg = rb0 + b, jg = j0 + jj;
            hdst[bg * HDIM + jg] = h;
            ys[((size_t)bg * SEQT + t) * HDIM + jg] = h;
            if (t == SEQT - 1) {
                hid_out [bg * HDIM + jg] = h;
                cell_out[bg * HDIM + jg] = c;
            }
        }

        // per-group barrier (32 CTAs), release/acquire; xp prefetch in the window
        if (t != SEQT - 1) {
            __syncthreads();                 // all h stores of this CTA issued
            unsigned* cptr = &g_cnt[grp][t];
            if (tid == 0) {
                asm volatile("red.release.gpu.global.add.u32 [%0], %1;"
                             :: "l"(cptr), "r"(1u) : "memory");
            }
            // prefetch next step's xp while group peers arrive
            #pragma unroll
            for (int e = 0; e < 4; ++e) {
                int idx = tid + e * 256;
                int b = idx >> 6, n = idx & 63;
                int g = (n >> 4) * HDIM + j0 + (n & 15);
                rxp[e] = g_xp[((size_t)(rb0 + b) * SEQT + (t + 1)) * G4 + g];
            }
            if (tid == 0) {
                unsigned v;
                do {
                    asm volatile("ld.acquire.gpu.global.u32 %0, [%1];"
                                 : "=r"(v) : "l"(cptr) : "memory");
                } while (v < (unsigned)SCAN_GRP);
            }
            __syncthreads();
        }
    }
}

// ---------------- launch ----------------
extern "C" void kernel_launch(void* const* d_in, const int* in_sizes, int n_in,
                              void* d_out, int out_size)
{
    const float* x     = (const float*)d_in[0];
    const float* W_ih0 = (const float*)d_in[1];
    const float* W_hh0 = (const float*)d_in[2];
    const float* b_ih0 = (const float*)d_in[3];
    const float* b_hh0 = (const float*)d_in[4];
    const float* W_ih1 = (const float*)d_in[5];
    const float* W_hh1 = (const float*)d_in[6];
    const float* b_ih1 = (const float*)d_in[7];
    const float* b_hh1 = (const float*)d_in[8];
    float* out = (float*)d_out;

    float *p_xt = nullptr, *p_ys0 = nullptr, *p_xp = nullptr;
    cudaGetSymbolAddress((void**)&p_xt,  g_xt);
    cudaGetSymbolAddress((void**)&p_ys0, g_ys0);
    cudaGetSymbolAddress((void**)&p_xp,  g_xp);

    const size_t OUT_BTH = (size_t)BATCH * SEQT * HDIM;   // 33,554,432
    float* hid0  = out + OUT_BTH;
    float* hid1  = hid0 + BATCH * HDIM;
    float* cell0 = out + OUT_BTH + 2 * BATCH * HDIM;
    float* cell1 = cell0 + BATCH * HDIM;

    const int scan_smem = (64 * WLD + 16 * WLD + 2 * 16 * GLD + 64) * sizeof(float);
    cudaFuncSetAttribute(scan_kernel, cudaFuncAttributeMaxDynamicSharedMemorySize, scan_smem);
    const int gemm_smem = 2 * 2 * GBM * SLD * sizeof(float);   // 81920
    cudaFuncSetAttribute(gemm_tf32_kernel, cudaFuncAttributeMaxDynamicSharedMemorySize, gemm_smem);

    // 1) transpose x -> (B,T,I)
    transpose_kernel<<<dim3(SEQT / 32, IDIM / 32, BATCH), dim3(32, 8)>>>(x);

    // 2) xp0 = xt @ W_ih0^T
    gemm_tf32_kernel<<<dim3(G4 / GBN, (BATCH * SEQT) / GBM), 256, gemm_smem>>>(p_xt, W_ih0, p_xp, IDIM);

    // 3) layer-0 scan
    zero_kernel<<<256, 256>>>();
    scan_kernel<<<SCAN_NB, SCAN_THREADS, scan_smem>>>(W_hh0, b_ih0, b_hh0, p_ys0, hid0, cell0);

    // 4) xp1 = ys0 @ W_ih1^T
    gemm_tf32_kernel<<<dim3(G4 / GBN, (BATCH * SEQT) / GBM), 256, gemm_smem>>>(p_ys0, W_ih1, p_xp, HDIM);

    // 5) layer-1 scan (writes directly into d_out)
    zero_kernel<<<256, 256>>>();
    scan_kernel<<<SCAN_NB, SCAN_THREADS, scan_smem>>>(W_hh1, b_ih1, b_hh1, out, hid1, cell1);
}

// round 5
// speedup vs baseline: 1.7955x; 1.2169x over previous
#include <cuda_runtime.h>
#include <mma.h>
#include <cstdint>

using namespace nvcuda;

#define BATCH 64
#define SEQT  1024
#define IDIM  256
#define HDIM  512
#define G4    2048   // 4*H

// ---------------- scratch (device globals; no allocation allowed) ----------------
__device__ float g_xt [(size_t)BATCH * SEQT * IDIM]; // transposed input (B,T,I)
__device__ float g_xp [(size_t)BATCH * SEQT * G4];   // precomputed input gates (B*T, 4H)
__device__ float g_ys0[(size_t)BATCH * SEQT * HDIM]; // layer-0 outputs
__device__ float g_h  [2][BATCH * HDIM];             // h double buffer
__device__ unsigned g_cnt[4][SEQT];                  // per-group per-step barrier counters

// ---------------- transpose: x (B,I,T) -> xt (B,T,I) ----------------
__global__ void transpose_kernel(const float* __restrict__ x) {
    __shared__ float tile[32][33];
    int b  = blockIdx.z;
    int t0 = blockIdx.x * 32;
    int i0 = blockIdx.y * 32;
    const float* xb = x + (size_t)b * IDIM * SEQT;
    #pragma unroll
    for (int k = 0; k < 32; k += 8) {
        int i = i0 + threadIdx.y + k;
        tile[threadIdx.y + k][threadIdx.x] = xb[(size_t)i * SEQT + t0 + threadIdx.x];
    }
    __syncthreads();
    float* xtb = g_xt + (size_t)b * SEQT * IDIM;
    #pragma unroll
    for (int k = 0; k < 32; k += 8) {
        int t = t0 + threadIdx.y + k;
        xtb[(size_t)t * IDIM + i0 + threadIdx.x] = tile[threadIdx.x][threadIdx.y + k];
    }
}

// ---------------- zero h buffers + barrier counters ----------------
__global__ void zero_kernel() {
    int i = blockIdx.x * blockDim.x + threadIdx.x;
    int n = 2 * BATCH * HDIM;
    float* h = &g_h[0][0];
    for (int k = i; k < n; k += gridDim.x * blockDim.x) h[k] = 0.0f;
    unsigned* c = &g_cnt[0][0];
    for (int k = i; k < 4 * SEQT; k += gridDim.x * blockDim.x) c[k] = 0u;
}

// ---------------- TF32 GEMM:  C[m,n] = sum_k A[m,k] * W[n,k] ----------------
#define GBM 128
#define GBN 128
#define GBK 32
#define SLD 40   // smem leading dim (32 + 8 pad)

__global__ void __launch_bounds__(256) gemm_tf32_kernel(
    const float* __restrict__ A, const float* __restrict__ W,
    float* __restrict__ C, int K)
{
    extern __shared__ float gs[];   // 2 stages x (sA 128xSLD + sB 128xSLD)
    int tid = threadIdx.x;
    int m0  = blockIdx.y * GBM;
    int n0  = blockIdx.x * GBN;
    int warp = tid >> 5;
    int wm = warp >> 2;   // 0..1 : 64 rows each
    int wn = warp & 3;    // 0..3 : 32 cols each

    wmma::fragment<wmma::accumulator, 16, 16, 8, float> cf[4][2];
    #pragma unroll
    for (int i = 0; i < 4; ++i)
        #pragma unroll
        for (int j = 0; j < 2; ++j)
            wmma::fill_fragment(cf[i][j], 0.0f);

    float4 ra[4], rb[4];

    auto ldg_tile = [&](int k0) {
        #pragma unroll
        for (int i = 0; i < 4; ++i) {
            int fid = tid + i * 256;
            int r = fid >> 3, cq = (fid & 7) << 2;
            ra[i] = *(const float4*)&A[(size_t)(m0 + r) * K + k0 + cq];
            rb[i] = *(const float4*)&W[(size_t)(n0 + r) * K + k0 + cq];
        }
    };
    auto sts_tile = [&](int buf) {
        float* sA = gs + buf * 2 * GBM * SLD;
        float* sB = sA + GBM * SLD;
        #pragma unroll
        for (int i = 0; i < 4; ++i) {
            int fid = tid + i * 256;
            int r = fid >> 3, cq = (fid & 7) << 2;
            float* d = &sA[r * SLD + cq];
            d[0] = wmma::__float_to_tf32(ra[i].x);
            d[1] = wmma::__float_to_tf32(ra[i].y);
            d[2] = wmma::__float_to_tf32(ra[i].z);
            d[3] = wmma::__float_to_tf32(ra[i].w);
            float* e = &sB[r * SLD + cq];
            e[0] = wmma::__float_to_tf32(rb[i].x);
            e[1] = wmma::__float_to_tf32(rb[i].y);
            e[2] = wmma::__float_to_tf32(rb[i].z);
            e[3] = wmma::__float_to_tf32(rb[i].w);
        }
    };

    ldg_tile(0);
    sts_tile(0);
    __syncthreads();

    int nk = K / GBK;
    int buf = 0;
    for (int kt = 0; kt < nk; ++kt) {
        bool has_next = (kt + 1) < nk;
        if (has_next) ldg_tile((kt + 1) * GBK);

        float* sA = gs + buf * 2 * GBM * SLD;
        float* sB = sA + GBM * SLD;
        #pragma unroll
        for (int ks = 0; ks < GBK; ks += 8) {
            wmma::fragment<wmma::matrix_a, 16, 16, 8, wmma::precision::tf32, wmma::row_major> af[4];
            wmma::fragment<wmma::matrix_b, 16, 16, 8, wmma::precision::tf32, wmma::col_major> bf[2];
            #pragma unroll
            for (int i = 0; i < 4; ++i)
                wmma::load_matrix_sync(af[i], &sA[(wm * 64 + i * 16) * SLD + ks], SLD);
            #pragma unroll
            for (int j = 0; j < 2; ++j)
                wmma::load_matrix_sync(bf[j], &sB[(wn * 32 + j * 16) * SLD + ks], SLD);
            #pragma unroll
            for (int i = 0; i < 4; ++i)
                #pragma unroll
                for (int j = 0; j < 2; ++j)
                    wmma::mma_sync(cf[i][j], af[i], bf[j], cf[i][j]);
        }
        if (has_next) sts_tile(buf ^ 1);
        __syncthreads();
        buf ^= 1;
    }
    #pragma unroll
    for (int i = 0; i < 4; ++i)
        #pragma unroll
        for (int j = 0; j < 2; ++j)
            wmma::store_matrix_sync(
                &C[(size_t)(m0 + wm * 64 + i * 16) * G4 + n0 + wn * 32 + j * 16],
                cf[i][j], G4, wmma::mem_row_major);
}

// ---------------- persistent LSTM scan (one layer) ----------------
// 128 CTAs x 512 threads. CTA: batch rows rb0..+15, hidden cols j0..+15.
// 16 warps = (nh 0..1) x (kq 0..7). Warp MMA tile: M16 x N32 x K64, with the
// WEIGHT fragments register-resident for the whole scan. K partials land in
// smem and are reduced in the fused reduce+elementwise phase.
#define SCAN_NB      128
#define SCAN_THREADS 512
#define SCAN_GRP     32     // CTAs per barrier group
#define WLD 520             // sH leading dim (mult of 4: ldm 16B rule)
#define PLD 68              // partial tile leading dim — MUST be mult of 4 for wmma ldm
#define TLD 68              // weight-init staging leading dim

__global__ void __launch_bounds__(SCAN_THREADS, 1) scan_kernel(
    const float* __restrict__ W_hh, const float* __restrict__ b_ih,
    const float* __restrict__ b_hh, float* __restrict__ ys,
    float* __restrict__ hid_out, float* __restrict__ cell_out)
{
    extern __shared__ float sm[];
    float* sH    = sm;                    // 16 x 520
    float* sPart = sH + 16 * WLD;         // 8 x 16 x PLD (also reused as weight-init staging)

    int tid  = threadIdx.x;
    int cta  = blockIdx.x;
    int grp  = cta >> 5;          // batch group 0..3
    int rb0  = grp * 16;          // batch-tile origin
    int j0   = (cta & 31) * 16;   // hidden-tile origin
    int warp = tid >> 5;          // 16 warps
    int nh   = warp & 1;          // N half: gate cols [nh*32, +32)
    int kq   = warp >> 1;         // K eighth: k in [kq*64, +64)

    // ---- load register-resident weight fragments (16 per warp) ----
    wmma::fragment<wmma::matrix_b, 16, 16, 8, wmma::precision::tf32, wmma::col_major> bfr[8][2];
    {
        float* sTmp = sPart;   // 64 x TLD staging, reused
        for (int q = 0; q < 8; ++q) {
            // stage W[n 0..63][k q*64..+64] as TF32
            for (int idx = tid; idx < 64 * 64; idx += SCAN_THREADS) {
                int n = idx >> 6, kk = idx & 63;
                int g = (n >> 4) * HDIM + j0 + (n & 15);
                sTmp[n * TLD + kk] =
                    wmma::__float_to_tf32(W_hh[(size_t)g * HDIM + q * 64 + kk]);
            }
            __syncthreads();
            if (q == kq) {
                #pragma unroll
                for (int s = 0; s < 8; ++s)
                    #pragma unroll
                    for (int j = 0; j < 2; ++j)
                        wmma::load_matrix_sync(bfr[s][j],
                            &sTmp[(nh * 32 + j * 16) * TLD + s * 8], TLD);
            }
            __syncthreads();
        }
    }

    // ---- per-cell state for the 256 active elementwise threads ----
    int b_  = tid >> 4;        // 0..15 for tid<256
    int jj_ = tid & 15;
    float bias[4];
    if (tid < 256) {
        #pragma unroll
        for (int q = 0; q < 4; ++q) {
            int g = q * HDIM + j0 + jj_;
            bias[q] = b_ih[g] + b_hh[g];
        }
    }
    float creg = 0.0f;

    // prefetch xp for t = 0
    float rxp[4];
    if (tid < 256) {
        #pragma unroll
        for (int q = 0; q < 4; ++q)
            rxp[q] = g_xp[((size_t)(rb0 + b_) * SEQT + 0) * G4 + q * HDIM + j0 + jj_];
    }

    for (int t = 0; t < SEQT; ++t) {
        const float* hsrc = g_h[t & 1];
        float*       hdst = g_h[(t + 1) & 1];

        // stage h tile (16 x 512) -> TF32 smem; __ldcv bypasses L1
        #pragma unroll
        for (int e = 0; e < 4; ++e) {
            int q = tid + e * SCAN_THREADS;
            int b = q >> 7; int c4 = (q & 127) << 2;
            float4 v = __ldcv((const float4*)&hsrc[(rb0 + b) * HDIM + c4]);
            float* d = &sH[b * WLD + c4];
            d[0] = wmma::__float_to_tf32(v.x);
            d[1] = wmma::__float_to_tf32(v.y);
            d[2] = wmma::__float_to_tf32(v.z);
            d[3] = wmma::__float_to_tf32(v.w);
        }
        __syncthreads();

        // partial gates: acc[j] = sum over this warp's K64 of h @ W^T
        {
            wmma::fragment<wmma::accumulator, 16, 16, 8, float> acc[2];
            wmma::fill_fragment(acc[0], 0.0f);
            wmma::fill_fragment(acc[1], 0.0f);
            #pragma unroll
            for (int s = 0; s < 8; ++s) {
                wmma::fragment<wmma::matrix_a, 16, 16, 8, wmma::precision::tf32, wmma::row_major> af;
                wmma::load_matrix_sync(af, &sH[kq * 64 + s * 8], WLD);
                wmma::mma_sync(acc[0], af, bfr[s][0], acc[0]);
                wmma::mma_sync(acc[1], af, bfr[s][1], acc[1]);
            }
            float* dst = &sPart[kq * 16 * PLD + nh * 32];
            wmma::store_matrix_sync(dst,      acc[0], PLD, wmma::mem_row_major);
            wmma::store_matrix_sync(dst + 16, acc[1], PLD, wmma::mem_row_major);
        }
        __syncthreads();

        // fused K-reduce + elementwise (tid < 256: one (b,jj) cell each)
        if (tid < 256) {
            float gs_[4];
            #pragma unroll
            for (int q = 0; q < 4; ++q) {
                float g = rxp[q] + bias[q];
                int col = q * 16 + jj_;
                #pragma unroll
                for (int p = 0; p < 8; ++p)
                    g += sPart[p * 16 * PLD + b_ * PLD + col];
                gs_[q] = g;
            }
            float si = 1.0f / (1.0f + __expf(-gs_[0]));
            float sf = 1.0f / (1.0f + __expf(-gs_[1]));
            float tg = tanhf(gs_[2]);
            float so = 1.0f / (1.0f + __expf(-gs_[3]));
            float c  = sf * creg + si * tg;
            creg = c;
            float h  = so * tanhf(c);
            int bg = rb0 + b_, jg = j0 + jj_;
            hdst[bg * HDIM + jg] = h;
            ys[((size_t)bg * SEQT + t) * HDIM + jg] = h;
            if (t == SEQT - 1) {
                hid_out [bg * HDIM + jg] = h;
                cell_out[bg * HDIM + jg] = c;
            }
        }

        // per-group barrier (32 CTAs), release/acquire; xp prefetch in the window
        if (t != SEQT - 1) {
            __syncthreads();                 // all h stores of this CTA issued
            unsigned* cptr = &g_cnt[grp][t];
            if (tid == 0) {
                asm volatile("red.release.gpu.global.add.u32 [%0], %1;"
                             :: "l"(cptr), "r"(1u) : "memory");
            }
            // prefetch next step's xp while group peers arrive
            if (tid < 256) {
                #pragma unroll
                for (int q = 0; q < 4; ++q)
                    rxp[q] = g_xp[((size_t)(rb0 + b_) * SEQT + (t + 1)) * G4
                                  + q * HDIM + j0 + jj_];
            }
            if (tid == 0) {
                unsigned v;
                do {
                    asm volatile("ld.acquire.gpu.global.u32 %0, [%1];"
                                 : "=r"(v) : "l"(cptr) : "memory");
                } while (v < (unsigned)SCAN_GRP);
            }
            __syncthreads();
        }
    }
}

// ---------------- launch ----------------
extern "C" void kernel_launch(void* const* d_in, const int* in_sizes, int n_in,
                              void* d_out, int out_size)
{
    const float* x     = (const float*)d_in[0];
    const float* W_ih0 = (const float*)d_in[1];
    const float* W_hh0 = (const float*)d_in[2];
    const float* b_ih0 = (const float*)d_in[3];
    const float* b_hh0 = (const float*)d_in[4];
    const float* W_ih1 = (const float*)d_in[5];
    const float* W_hh1 = (const float*)d_in[6];
    const float* b_ih1 = (const float*)d_in[7];
    const float* b_hh1 = (const float*)d_in[8];
    float* out = (float*)d_out;

    float *p_xt = nullptr, *p_ys0 = nullptr, *p_xp = nullptr;
    cudaGetSymbolAddress((void**)&p_xt,  g_xt);
    cudaGetSymbolAddress((void**)&p_ys0, g_ys0);
    cudaGetSymbolAddress((void**)&p_xp,  g_xp);

    const size_t OUT_BTH = (size_t)BATCH * SEQT * HDIM;   // 33,554,432
    float* hid0  = out + OUT_BTH;
    float* hid1  = hid0 + BATCH * HDIM;
    float* cell0 = out + OUT_BTH + 2 * BATCH * HDIM;
    float* cell1 = cell0 + BATCH * HDIM;

    const int scan_smem = (16 * WLD + 8 * 16 * PLD) * sizeof(float);
    cudaFuncSetAttribute(scan_kernel, cudaFuncAttributeMaxDynamicSharedMemorySize, scan_smem);
    const int gemm_smem = 2 * 2 * GBM * SLD * sizeof(float);   // 81920
    cudaFuncSetAttribute(gemm_tf32_kernel, cudaFuncAttributeMaxDynamicSharedMemorySize, gemm_smem);

    // 1) transpose x -> (B,T,I)
    transpose_kernel<<<dim3(SEQT / 32, IDIM / 32, BATCH), dim3(32, 8)>>>(x);

    // 2) xp0 = xt @ W_ih0^T
    gemm_tf32_kernel<<<dim3(G4 / GBN, (BATCH * SEQT) / GBM), 256, gemm_smem>>>(p_xt, W_ih0, p_xp, IDIM);

    // 3) layer-0 scan
    zero_kernel<<<256, 256>>>();
    scan_kernel<<<SCAN_NB, SCAN_THREADS, scan_smem>>>(W_hh0, b_ih0, b_hh0, p_ys0, hid0, cell0);

    // 4) xp1 = ys0 @ W_ih1^T
    gemm_tf32_kernel<<<dim3(G4 / GBN, (BATCH * SEQT) / GBM), 256, gemm_smem>>>(p_ys0, W_ih1, p_xp, HDIM);

    // 5) layer-1 scan (writes directly into d_out)
    zero_kernel<<<256, 256>>>();
    scan_kernel<<<SCAN_NB, SCAN_THREADS, scan_smem>>>(W_hh1, b_ih1, b_hh1, out, hid1, cell1);
}

// round 7
// speedup vs baseline: 1.9015x; 1.0590x over previous
#include <cuda_runtime.h>
#include <mma.h>
#include <cstdint>

using namespace nvcuda;

#define BATCH 64
#define SEQT  1024
#define IDIM  256
#define HDIM  512
#define G4    2048   // 4*H

// ---------------- scratch (device globals; no allocation allowed) ----------------
__device__ float g_xt [(size_t)BATCH * SEQT * IDIM]; // transposed input (B,T,I)
__device__ float g_xp [(size_t)BATCH * SEQT * G4];   // precomputed input gates (B*T, 4H)
__device__ float g_ys0[(size_t)BATCH * SEQT * HDIM]; // layer-0 outputs
__device__ float g_h  [2][BATCH * HDIM];             // h double buffer
__device__ unsigned g_cnt[4][SEQT];                  // per-group per-step barrier counters

// ---------------- transpose: x (B,I,T) -> xt (B,T,I) ----------------
__global__ void transpose_kernel(const float* __restrict__ x) {
    __shared__ float tile[32][33];
    int b  = blockIdx.z;
    int t0 = blockIdx.x * 32;
    int i0 = blockIdx.y * 32;
    const float* xb = x + (size_t)b * IDIM * SEQT;
    #pragma unroll
    for (int k = 0; k < 32; k += 8) {
        int i = i0 + threadIdx.y + k;
        tile[threadIdx.y + k][threadIdx.x] = xb[(size_t)i * SEQT + t0 + threadIdx.x];
    }
    __syncthreads();
    float* xtb = g_xt + (size_t)b * SEQT * IDIM;
    #pragma unroll
    for (int k = 0; k < 32; k += 8) {
        int t = t0 + threadIdx.y + k;
        xtb[(size_t)t * IDIM + i0 + threadIdx.x] = tile[threadIdx.x][threadIdx.y + k];
    }
}

// ---------------- zero h buffers + barrier counters ----------------
__global__ void zero_kernel() {
    int i = blockIdx.x * blockDim.x + threadIdx.x;
    int n = 2 * BATCH * HDIM;
    float* h = &g_h[0][0];
    for (int k = i; k < n; k += gridDim.x * blockDim.x) h[k] = 0.0f;
    unsigned* c = &g_cnt[0][0];
    for (int k = i; k < 4 * SEQT; k += gridDim.x * blockDim.x) c[k] = 0u;
}

// ---------------- TF32 GEMM:  C[m,n] = sum_k A[m,k] * W[n,k] ----------------
#define GBM 128
#define GBN 128
#define GBK 64
#define SLD 72   // smem leading dim (64 + 8 pad)

__global__ void __launch_bounds__(256) gemm_tf32_kernel(
    const float* __restrict__ A, const float* __restrict__ W,
    float* __restrict__ C, int K)
{
    extern __shared__ float gs[];   // 2 stages x (sA 128xSLD + sB 128xSLD)
    int tid = threadIdx.x;
    int m0  = blockIdx.y * GBM;
    int n0  = blockIdx.x * GBN;
    int warp = tid >> 5;
    int wm = warp >> 2;   // 0..1 : 64 rows each
    int wn = warp & 3;    // 0..3 : 32 cols each

    wmma::fragment<wmma::accumulator, 16, 16, 8, float> cf[4][2];
    #pragma unroll
    for (int i = 0; i < 4; ++i)
        #pragma unroll
        for (int j = 0; j < 2; ++j)
            wmma::fill_fragment(cf[i][j], 0.0f);

    float4 ra[8], rb[8];

    auto ldg_tile = [&](int k0) {
        #pragma unroll
        for (int i = 0; i < 8; ++i) {
            int fid = tid + i * 256;
            int r = fid >> 4, c4 = (fid & 15) << 2;
            ra[i] = *(const float4*)&A[(size_t)(m0 + r) * K + k0 + c4];
            rb[i] = *(const float4*)&W[(size_t)(n0 + r) * K + k0 + c4];
        }
    };
    auto sts_tile = [&](int buf) {
        float* sA = gs + buf * 2 * GBM * SLD;
        float* sB = sA + GBM * SLD;
        #pragma unroll
        for (int i = 0; i < 8; ++i) {
            int fid = tid + i * 256;
            int r = fid >> 4, c4 = (fid & 15) << 2;
            float* d = &sA[r * SLD + c4];
            d[0] = wmma::__float_to_tf32(ra[i].x);
            d[1] = wmma::__float_to_tf32(ra[i].y);
            d[2] = wmma::__float_to_tf32(ra[i].z);
            d[3] = wmma::__float_to_tf32(ra[i].w);
            float* e = &sB[r * SLD + c4];
            e[0] = wmma::__float_to_tf32(rb[i].x);
            e[1] = wmma::__float_to_tf32(rb[i].y);
            e[2] = wmma::__float_to_tf32(rb[i].z);
            e[3] = wmma::__float_to_tf32(rb[i].w);
        }
    };

    ldg_tile(0);
    sts_tile(0);
    __syncthreads();

    int nk = K / GBK;
    int buf = 0;
    for (int kt = 0; kt < nk; ++kt) {
        bool has_next = (kt + 1) < nk;
        if (has_next) ldg_tile((kt + 1) * GBK);

        float* sA = gs + buf * 2 * GBM * SLD;
        float* sB = sA + GBM * SLD;
        #pragma unroll
        for (int ks = 0; ks < GBK; ks += 8) {
            wmma::fragment<wmma::matrix_a, 16, 16, 8, wmma::precision::tf32, wmma::row_major> af[4];
            wmma::fragment<wmma::matrix_b, 16, 16, 8, wmma::precision::tf32, wmma::col_major> bf[2];
            #pragma unroll
            for (int i = 0; i < 4; ++i)
                wmma::load_matrix_sync(af[i], &sA[(wm * 64 + i * 16) * SLD + ks], SLD);
            #pragma unroll
            for (int j = 0; j < 2; ++j)
                wmma::load_matrix_sync(bf[j], &sB[(wn * 32 + j * 16) * SLD + ks], SLD);
            #pragma unroll
            for (int i = 0; i < 4; ++i)
                #pragma unroll
                for (int j = 0; j < 2; ++j)
                    wmma::mma_sync(cf[i][j], af[i], bf[j], cf[i][j]);
        }
        if (has_next) sts_tile(buf ^ 1);
        __syncthreads();
        buf ^= 1;
    }
    #pragma unroll
    for (int i = 0; i < 4; ++i)
        #pragma unroll
        for (int j = 0; j < 2; ++j)
            wmma::store_matrix_sync(
                &C[(size_t)(m0 + wm * 64 + i * 16) * G4 + n0 + wn * 32 + j * 16],
                cf[i][j], G4, wmma::mem_row_major);
}

// ---------------- persistent LSTM scan (one layer) ----------------
// 128 CTAs x 512 threads. CTA: batch rows rb0..+15, hidden cols j0..+15.
// 16 warps = (nh 0..1) x (kq 0..7), weight fragments register-resident.
// Per step: all-lane acquire poll -> per-pair staging (named barrier) ->
// MMA partials -> BAR -> fused reduce+elementwise -> BAR -> release.
#define SCAN_NB      128
#define SCAN_THREADS 512
#define SCAN_GRP     32     // CTAs per barrier group
#define WLD 520             // sH leading dim (mult of 4)
#define PLD 68              // partial tile leading dim (mult of 4)
#define TLD 68              // weight-init staging leading dim

__global__ void __launch_bounds__(SCAN_THREADS, 1) scan_kernel(
    const float* __restrict__ W_hh, const float* __restrict__ b_ih,
    const float* __restrict__ b_hh, float* __restrict__ ys,
    float* __restrict__ hid_out, float* __restrict__ cell_out)
{
    extern __shared__ float sm[];
    float* sH    = sm;                    // 16 x 520
    float* sPart = sH + 16 * WLD;         // 8 x 16 x PLD (also reused as weight-init staging)

    int tid  = threadIdx.x;
    int lane = tid & 31;
    int cta  = blockIdx.x;
    int grp  = cta >> 5;          // batch group 0..3
    int rb0  = grp * 16;          // batch-tile origin
    int j0   = (cta & 31) * 16;   // hidden-tile origin
    int warp = tid >> 5;          // 16 warps
    int nh   = warp & 1;          // N half: gate cols [nh*32, +32)
    int kq   = warp >> 1;         // K eighth: k in [kq*64, +64)

    // ---- load register-resident weight fragments (16 per warp) ----
    wmma::fragment<wmma::matrix_b, 16, 16, 8, wmma::precision::tf32, wmma::col_major> bfr[8][2];
    {
        float* sTmp = sPart;   // 64 x TLD staging, reused
        for (int q = 0; q < 8; ++q) {
            for (int idx = tid; idx < 64 * 64; idx += SCAN_THREADS) {
                int n = idx >> 6, kk = idx & 63;
                int g = (n >> 4) * HDIM + j0 + (n & 15);
                sTmp[n * TLD + kk] =
                    wmma::__float_to_tf32(W_hh[(size_t)g * HDIM + q * 64 + kk]);
            }
            __syncthreads();
            if (q == kq) {
                #pragma unroll
                for (int s = 0; s < 8; ++s)
                    #pragma unroll
                    for (int j = 0; j < 2; ++j)
                        wmma::load_matrix_sync(bfr[s][j],
                            &sTmp[(nh * 32 + j * 16) * TLD + s * 8], TLD);
            }
            __syncthreads();
        }
    }

    // ---- per-cell state for the 256 active elementwise threads ----
    int b_  = tid >> 4;        // 0..15 for tid<256
    int jj_ = tid & 15;
    float bias[4];
    if (tid < 256) {
        #pragma unroll
        for (int q = 0; q < 4; ++q) {
            int g = q * HDIM + j0 + jj_;
            bias[q] = b_ih[g] + b_hh[g];
        }
    }
    float creg = 0.0f;

    // prefetch xp for t = 0
    float rxp[4];
    if (tid < 256) {
        #pragma unroll
        for (int q = 0; q < 4; ++q)
            rxp[q] = g_xp[((size_t)(rb0 + b_) * SEQT + 0) * G4 + q * HDIM + j0 + jj_];
    }

    for (int t = 0; t < SEQT; ++t) {
        // wait for previous step's h from all group peers (all-lane acquire poll)
        if (t > 0) {
            const unsigned* cptr = &g_cnt[grp][t - 1];
            unsigned v;
            do {
                asm volatile("ld.acquire.gpu.global.u32 %0, [%1];"
                             : "=r"(v) : "l"(cptr) : "memory");
            } while (v < (unsigned)SCAN_GRP);
        }

        const float* hsrc = g_h[t & 1];
        float*       hdst = g_h[(t + 1) & 1];

        // stage OWN K-slice of h: warp (kq, nh) stages rows nh*8..+8, cols kq*64..+64
        {
            const float* src = &hsrc[rb0 * HDIM + kq * 64];
            #pragma unroll
            for (int e = 0; e < 4; ++e) {
                int idx = e * 32 + lane;        // 0..127
                int r   = nh * 8 + (idx >> 4);  // row in tile
                int c4  = (idx & 15) << 2;      // col within slice
                float4 v = __ldcv((const float4*)&src[r * HDIM + c4]);
                float* d = &sH[r * WLD + kq * 64 + c4];
                d[0] = wmma::__float_to_tf32(v.x);
                d[1] = wmma::__float_to_tf32(v.y);
                d[2] = wmma::__float_to_tf32(v.z);
                d[3] = wmma::__float_to_tf32(v.w);
            }
        }
        // sync only with pair partner (other nh of same kq): named barrier, 64 threads
        asm volatile("bar.sync %0, %1;" :: "r"(kq + 1), "r"(64) : "memory");

        // partial gates: acc[j] = sum over this warp's K64 of h @ W^T
        {
            wmma::fragment<wmma::accumulator, 16, 16, 8, float> acc[2];
            wmma::fill_fragment(acc[0], 0.0f);
            wmma::fill_fragment(acc[1], 0.0f);
            #pragma unroll
            for (int s = 0; s < 8; ++s) {
                wmma::fragment<wmma::matrix_a, 16, 16, 8, wmma::precision::tf32, wmma::row_major> af;
                wmma::load_matrix_sync(af, &sH[kq * 64 + s * 8], WLD);
                wmma::mma_sync(acc[0], af, bfr[s][0], acc[0]);
                wmma::mma_sync(acc[1], af, bfr[s][1], acc[1]);
            }
            float* dst = &sPart[kq * 16 * PLD + nh * 32];
            wmma::store_matrix_sync(dst,      acc[0], PLD, wmma::mem_row_major);
            wmma::store_matrix_sync(dst + 16, acc[1], PLD, wmma::mem_row_major);
        }
        __syncthreads();

        // fused K-reduce + elementwise (tid < 256: one (b,jj) cell each)
        if (tid < 256) {
            float gs_[4];
            #pragma unroll
            for (int q = 0; q < 4; ++q) {
                float g = rxp[q] + bias[q];
                int col = q * 16 + jj_;
                #pragma unroll
                for (int p = 0; p < 8; ++p)
                    g += sPart[p * 16 * PLD + b_ * PLD + col];
                gs_[q] = g;
            }
            float si = 1.0f / (1.0f + __expf(-gs_[0]));
            float sf = 1.0f / (1.0f + __expf(-gs_[1]));
            float tg = tanhf(gs_[2]);
            float so = 1.0f / (1.0f + __expf(-gs_[3]));
            float c  = sf * creg + si * tg;
            creg = c;
            float h  = so * tanhf(c);
            int bg = rb0 + b_, jg = j0 + jj_;
            hdst[bg * HDIM + jg] = h;
            ys[((size_t)bg * SEQT + t) * HDIM + jg] = h;
            if (t == SEQT - 1) {
                hid_out [bg * HDIM + jg] = h;
                cell_out[bg * HDIM + jg] = c;
            }
        }
        __syncthreads();   // h stores complete before arrival

        if (t != SEQT - 1) {
            if (tid == 0) {
                asm volatile("red.release.gpu.global.add.u32 [%0], %1;"
                             :: "l"(&g_cnt[grp][t]), "r"(1u) : "memory");
            }
            // prefetch next step's xp while peers arrive
            if (tid < 256) {
                #pragma unroll
                for (int q = 0; q < 4; ++q)
                    rxp[q] = g_xp[((size_t)(rb0 + b_) * SEQT + (t + 1)) * G4
                                  + q * HDIM + j0 + jj_];
            }
        }
    }
}

// ---------------- launch ----------------
extern "C" void kernel_launch(void* const* d_in, const int* in_sizes, int n_in,
                              void* d_out, int out_size)
{
    const float* x     = (const float*)d_in[0];
    const float* W_ih0 = (const float*)d_in[1];
    const float* W_hh0 = (const float*)d_in[2];
    const float* b_ih0 = (const float*)d_in[3];
    const float* b_hh0 = (const float*)d_in[4];
    const float* W_ih1 = (const float*)d_in[5];
    const float* W_hh1 = (const float*)d_in[6];
    const float* b_ih1 = (const float*)d_in[7];
    const float* b_hh1 = (const float*)d_in[8];
    float* out = (float*)d_out;

    float *p_xt = nullptr, *p_ys0 = nullptr, *p_xp = nullptr;
    cudaGetSymbolAddress((void**)&p_xt,  g_xt);
    cudaGetSymbolAddress((void**)&p_ys0, g_ys0);
    cudaGetSymbolAddress((void**)&p_xp,  g_xp);

    const size_t OUT_BTH = (size_t)BATCH * SEQT * HDIM;   // 33,554,432
    float* hid0  = out + OUT_BTH;
    float* hid1  = hid0 + BATCH * HDIM;
    float* cell0 = out + OUT_BTH + 2 * BATCH * HDIM;
    float* cell1 = cell0 + BATCH * HDIM;

    const int scan_smem = (16 * WLD + 8 * 16 * PLD) * sizeof(float);
    cudaFuncSetAttribute(scan_kernel, cudaFuncAttributeMaxDynamicSharedMemorySize, scan_smem);
    const int gemm_smem = 2 * 2 * GBM * SLD * sizeof(float);   // 147456
    cudaFuncSetAttribute(gemm_tf32_kernel, cudaFuncAttributeMaxDynamicSharedMemorySize, gemm_smem);

    // 1) transpose x -> (B,T,I)
    transpose_kernel<<<dim3(SEQT / 32, IDIM / 32, BATCH), dim3(32, 8)>>>(x);

    // 2) xp0 = xt @ W_ih0^T
    gemm_tf32_kernel<<<dim3(G4 / GBN, (BATCH * SEQT) / GBM), 256, gemm_smem>>>(p_xt, W_ih0, p_xp, IDIM);

    // 3) layer-0 scan
    zero_kernel<<<256, 256>>>();
    scan_kernel<<<SCAN_NB, SCAN_THREADS, scan_smem>>>(W_hh0, b_ih0, b_hh0, p_ys0, hid0, cell0);

    // 4) xp1 = ys0 @ W_ih1^T
    gemm_tf32_kernel<<<dim3(G4 / GBN, (BATCH * SEQT) / GBM), 256, gemm_smem>>>(p_ys0, W_ih1, p_xp, HDIM);

    // 5) layer-1 scan (writes directly into d_out)
    zero_kernel<<<256, 256>>>();
    scan_kernel<<<SCAN_NB, SCAN_THREADS, scan_smem>>>(W_hh1, b_ih1, b_hh1, out, hid1, cell1);
}